// round 2
// baseline (speedup 1.0000x reference)
#include <cuda_runtime.h>
#include <math.h>

// ---------------- problem constants ----------------
#define NNODES 147456
#define GDIM   48
#define NPB    2304          // nodes per batch (48*48)
#define D0 128
#define D1 102
#define D2 73
#define D3 44
#define D4 16
#define KK 3
#define XG (KK*D3)           // 132
#define CMB (XG+D3)          // 176

// ---------------- scratch (device globals; allocation-free) ----------------
__device__ float g_t0[NNODES*D1];     // 60 MB
__device__ float g_t1[NNODES*D2];     // 43 MB
__device__ float g_xr[NNODES*CMB];    // 104 MB
__device__ float g_h2[NNODES*D3];     // 26 MB
__device__ float g_part[25344*88];    // partial stats (also >= 1152*204)
__device__ float g_stats[256];
__device__ float g_w1f[D1*D2];
__device__ float g_bias1[D2];
__device__ float g_wcf[D2*CMB];
__device__ float g_biasc[CMB];
__device__ float g_w3f[D3*D4];
__device__ float g_bias3[D4];
__device__ float g_gw[27];            // [9 offsets][3 kernels]

// ---------------- helpers ----------------
__host__ __device__ constexpr int kpad16(int k) { return (k + 15) / 16 * 16; }
__host__ __device__ constexpr int gemm_smem_bytes(int K, int NC, bool S) {
    return (kpad16(K) * NC + 16 * 132 + (S ? 2 * NC : 0)) * 4;
}

// ---------------- GEMM: C[N x NC] = A[N x K] @ W[K x NC] + bias ----------------
// 128 rows per block, 256 threads, thread micro-tile = 8 rows x TN cols.
// Optionally emits per-block per-channel (sum, sumsq) partials for BN stats.
template <int K, int NC, bool STATS>
__global__ void __launch_bounds__(256)
gemm_k(const float* __restrict__ A, const float* __restrict__ W,
       const float* __restrict__ bias, float* __restrict__ C,
       float* __restrict__ part) {
    constexpr int KP = kpad16(K);
    constexpr int TN = (NC + 15) / 16;

    extern __shared__ float sm[];
    float* Ws   = sm;                    // KP * NC
    float* As   = Ws + KP * NC;          // [16][132]  (As[kk*132 + r])
    float* ssum = As + 16 * 132;         // NC   (STATS)
    float* ssq  = ssum + NC;             // NC   (STATS)

    const int tid = threadIdx.x;
    const int tx  = tid & 15;
    const int ty  = tid >> 4;
    const int row0 = blockIdx.x * 128;

    // stage weights (zero-padded rows K..KP-1)
    for (int e = tid; e < KP * NC; e += 256)
        Ws[e] = (e < K * NC) ? W[e] : 0.f;
    if (STATS) for (int e = tid; e < 2 * NC; e += 256) ssum[e] = 0.f;

    int cols[TN];
#pragma unroll
    for (int j = 0; j < TN; j++) {
        int c = tx + 16 * j;
        cols[j] = (c < NC) ? c : 0;
    }

    float acc[8][TN];
#pragma unroll
    for (int i = 0; i < 8; i++)
#pragma unroll
        for (int j = 0; j < TN; j++) acc[i][j] = 0.f;

    for (int k0 = 0; k0 < KP; k0 += 16) {
        __syncthreads();
        // stage A tile: 128 rows x 16 k, transposed to As[kk][r]
#pragma unroll
        for (int i = 0; i < 8; i++) {
            int e = tid + i * 256;
            int r = e >> 4, kk = e & 15;
            int k = k0 + kk;
            As[kk * 132 + r] = (k < K) ? A[(long)(row0 + r) * K + k] : 0.f;
        }
        __syncthreads();
#pragma unroll
        for (int kk = 0; kk < 16; kk++) {
            const float4 a0 = *(const float4*)&As[kk * 132 + ty * 8];
            const float4 a1 = *(const float4*)&As[kk * 132 + ty * 8 + 4];
            const float* wr = &Ws[(k0 + kk) * NC];
#pragma unroll
            for (int j = 0; j < TN; j++) {
                float w = wr[cols[j]];
                acc[0][j] += a0.x * w; acc[1][j] += a0.y * w;
                acc[2][j] += a0.z * w; acc[3][j] += a0.w * w;
                acc[4][j] += a1.x * w; acc[5][j] += a1.y * w;
                acc[6][j] += a1.z * w; acc[7][j] += a1.w * w;
            }
        }
    }

    // epilogue: bias, store, local stats
#pragma unroll
    for (int j = 0; j < TN; j++) {
        int c = tx + 16 * j;
        if (c < NC) {
            float bv = bias[c];
            float s = 0.f, q = 0.f;
#pragma unroll
            for (int i = 0; i < 8; i++) {
                float v = acc[i][j] + bv;
                C[(long)(row0 + ty * 8 + i) * NC + c] = v;
                s += v; q += v * v;
            }
            if (STATS) { atomicAdd(&ssum[c], s); atomicAdd(&ssq[c], q); }
        }
    }
    if (STATS) {
        __syncthreads();
        for (int c = tid; c < NC; c += 256) {
            part[(size_t)blockIdx.x * (2 * NC) + c]      = ssum[c];
            part[(size_t)blockIdx.x * (2 * NC) + NC + c] = ssq[c];
        }
    }
}

// ---------------- stage-2 reduction of per-block partials ----------------
__global__ void stage2_k(const float* __restrict__ part, float* __restrict__ stats,
                         int P, int C2) {
    int c = blockIdx.x;
    float s = 0.f;
    for (int p = threadIdx.x; p < P; p += 256) s += part[(size_t)p * C2 + c];
    __shared__ float sm[256];
    sm[threadIdx.x] = s; __syncthreads();
    for (int off = 128; off > 0; off >>= 1) {
        if (threadIdx.x < off) sm[threadIdx.x] += sm[threadIdx.x + off];
        __syncthreads();
    }
    if (threadIdx.x == 0) stats[c] = sm[0];
}

// ---------------- BN fold kernels ----------------
// BN(t) = t*s + c0 with s = gamma*rsqrt(var+eps), c0 = beta - mean*s.
// Then BN(t)@W + b = t@(diag(s)W) + (c0@W + b).
__global__ void fold0_k(const float* __restrict__ stats,
                        const float* __restrict__ gamma, const float* __restrict__ beta,
                        const float* __restrict__ w1, const float* __restrict__ b1,
                        float* __restrict__ w1f, float* __restrict__ bias1) {
    __shared__ float s0[D1], c0[D1];
    int tid = threadIdx.x;
    for (int c = tid; c < D1; c += 256) {
        float m = stats[c] * (1.f / NNODES);
        float v = stats[D1 + c] * (1.f / NNODES) - m * m;
        float s = gamma[c] * rsqrtf(v + 1e-5f);
        s0[c] = s; c0[c] = beta[c] - m * s;
    }
    __syncthreads();
    for (int e = tid; e < D1 * D2; e += 256) {
        int k = e / D2;
        w1f[e] = s0[k] * w1[e];
    }
    for (int j = tid; j < D2; j += 256) {
        float b = b1[j];
        for (int k = 0; k < D1; k++) b += c0[k] * w1[k * D2 + j];
        bias1[j] = b;
    }
}

__global__ void fold1_k(const float* __restrict__ stats,
                        const float* __restrict__ gamma, const float* __restrict__ beta,
                        const float* __restrict__ g2, const float* __restrict__ w2,
                        const float* __restrict__ b2,
                        const float* __restrict__ mu, const float* __restrict__ sigma,
                        float* __restrict__ wcf, float* __restrict__ biasc,
                        float* __restrict__ gw) {
    __shared__ float s1[D2], c1[D2];
    int tid = threadIdx.x;
    for (int c = tid; c < D2; c += 256) {
        float m = stats[c] * (1.f / NNODES);
        float v = stats[D2 + c] * (1.f / NNODES) - m * m;
        float s = gamma[c] * rsqrtf(v + 1e-5f);
        s1[c] = s; c1[c] = beta[c] - m * s;
    }
    __syncthreads();
    // combined weights: cols [0,132) from g2, cols [132,176) from w2 (root)
    for (int e = tid; e < D2 * CMB; e += 256) {
        int k = e / CMB, j = e - k * CMB;
        float w = (j < XG) ? g2[k * XG + j] : w2[k * D3 + (j - XG)];
        wcf[e] = s1[k] * w;
    }
    for (int j = tid; j < CMB; j += 256) {
        float b = (j < XG) ? 0.f : b2[j - XG];
        for (int k = 0; k < D2; k++)
            b += c1[k] * ((j < XG) ? g2[k * XG + j] : w2[k * D3 + (j - XG)]);
        biasc[j] = b;
    }
    // gaussian weights: 9 offsets x 3 kernels (ea = (dx,dy)*0.5 + 0.5)
    if (tid < 27) {
        int ci = tid / 3, k = tid % 3;
        int dx = ci / 3 - 1, dy = ci % 3 - 1;
        float ex = dx * 0.5f + 0.5f - mu[k * 2 + 0];
        float ey = dy * 0.5f + 0.5f - mu[k * 2 + 1];
        float sx = sigma[k * 2 + 0], sy = sigma[k * 2 + 1];
        gw[tid] = expf(-0.5f * (ex * ex / (1e-15f + sx * sx) +
                                ey * ey / (1e-15f + sy * sy)));
    }
}

__global__ void fold2_k(const float* __restrict__ stats,
                        const float* __restrict__ gamma, const float* __restrict__ beta,
                        const float* __restrict__ w3, const float* __restrict__ b3,
                        float* __restrict__ w3f, float* __restrict__ bias3) {
    __shared__ float s2[D3], c2[D3];
    int tid = threadIdx.x;
    for (int c = tid; c < D3; c += 256) {
        float m = stats[c] * (1.f / NNODES);
        float v = stats[D3 + c] * (1.f / NNODES) - m * m;
        float s = gamma[c] * rsqrtf(v + 1e-5f);
        s2[c] = s; c2[c] = beta[c] - m * s;
    }
    __syncthreads();
    for (int e = tid; e < D3 * D4; e += 256) {
        int k = e / D4;
        w3f[e] = s2[k] * w3[e];
    }
    for (int j = tid; j < D4; j += 256) {
        float b = b3[j];
        for (int k = 0; k < D3; k++) b += c2[k] * w3[k * D4 + j];
        bias3[j] = b;
    }
}

// ---------------- 9-point stencil (the GMM conv aggregation) ----------------
// xr: [N,176] = [xg(k*44+o) | root(o)].  h2[i,o] = (1/cnt) * sum over valid
// (dx,dy) of sum_k xg[nbr, k*44+o]*gw[(dx,dy),k]  + root[i,o]. Emits BN stats.
__global__ void __launch_bounds__(256)
stencil_k(const float* __restrict__ xr, const float* __restrict__ gw9,
          float* __restrict__ h2, float* __restrict__ part) {
    __shared__ float gws[27];
    __shared__ float ssum[D3], ssq[D3];
    int tid = threadIdx.x;
    if (tid < 27) gws[tid] = gw9[tid];
    if (tid < D3) { ssum[tid] = 0.f; ssq[tid] = 0.f; }
    __syncthreads();

    long idx = (long)blockIdx.x * 256 + tid;   // < N*44 exactly
    int node = (int)(idx / D3);
    int o    = (int)(idx - (long)node * D3);
    int r  = node % NPB;
    int ix = r / GDIM, iy = r % GDIM;

    int nvx = 3 - (ix == 0) - (ix == GDIM - 1);
    int nvy = 3 - (iy == 0) - (iy == GDIM - 1);
    float inv_cnt = 1.f / (float)(nvx * nvy);

    float acc = 0.f;
#pragma unroll
    for (int dx = -1; dx <= 1; dx++) {
        int jx = ix + dx;
        if (jx < 0 || jx >= GDIM) continue;
#pragma unroll
        for (int dy = -1; dy <= 1; dy++) {
            int jy = iy + dy;
            if (jy < 0 || jy >= GDIM) continue;
            const float* row = xr + (long)(node + dx * GDIM + dy) * CMB;
            const float* g   = gws + ((dx + 1) * 3 + (dy + 1)) * 3;
            acc += row[o] * g[0] + row[D3 + o] * g[1] + row[2 * D3 + o] * g[2];
        }
    }
    float v = acc * inv_cnt + xr[(long)node * CMB + XG + o];
    h2[idx] = v;
    atomicAdd(&ssum[o], v);
    atomicAdd(&ssq[o], v * v);
    __syncthreads();
    if (tid < D3) {
        part[(size_t)blockIdx.x * (2 * D3) + tid]      = ssum[tid];
        part[(size_t)blockIdx.x * (2 * D3) + D3 + tid] = ssq[tid];
    }
}

// ---------------- host launcher ----------------
extern "C" void kernel_launch(void* const* d_in, const int* in_sizes, int n_in,
                              void* d_out, int out_size) {
    const float* x      = (const float*)d_in[0];
    const float* w0     = (const float*)d_in[3];
    const float* b0     = (const float*)d_in[4];
    const float* gamma0 = (const float*)d_in[5];
    const float* beta0  = (const float*)d_in[6];
    const float* w1     = (const float*)d_in[7];
    const float* b1     = (const float*)d_in[8];
    const float* gamma1 = (const float*)d_in[9];
    const float* beta1  = (const float*)d_in[10];
    const float* w2     = (const float*)d_in[11];
    const float* g2     = (const float*)d_in[12];
    const float* mu2    = (const float*)d_in[13];
    const float* sigma2 = (const float*)d_in[14];
    const float* b2     = (const float*)d_in[15];
    const float* gamma2 = (const float*)d_in[16];
    const float* beta2  = (const float*)d_in[17];
    const float* w3     = (const float*)d_in[18];
    const float* b3     = (const float*)d_in[19];
    float* out = (float*)d_out;

    float *t0, *t1, *xr, *h2, *part, *stats, *w1f, *bias1, *wcf, *biasc, *w3f, *bias3, *gw;
    cudaGetSymbolAddress((void**)&t0,    g_t0);
    cudaGetSymbolAddress((void**)&t1,    g_t1);
    cudaGetSymbolAddress((void**)&xr,    g_xr);
    cudaGetSymbolAddress((void**)&h2,    g_h2);
    cudaGetSymbolAddress((void**)&part,  g_part);
    cudaGetSymbolAddress((void**)&stats, g_stats);
    cudaGetSymbolAddress((void**)&w1f,   g_w1f);
    cudaGetSymbolAddress((void**)&bias1, g_bias1);
    cudaGetSymbolAddress((void**)&wcf,   g_wcf);
    cudaGetSymbolAddress((void**)&biasc, g_biasc);
    cudaGetSymbolAddress((void**)&w3f,   g_w3f);
    cudaGetSymbolAddress((void**)&bias3, g_bias3);
    cudaGetSymbolAddress((void**)&gw,    g_gw);

    constexpr int SM0 = gemm_smem_bytes(D0, D1, true);
    constexpr int SM1 = gemm_smem_bytes(D1, D2, true);
    constexpr int SM2 = gemm_smem_bytes(D2, CMB, false);
    constexpr int SM3 = gemm_smem_bytes(D3, D4, false);
    cudaFuncSetAttribute(gemm_k<D0, D1, true>,   cudaFuncAttributeMaxDynamicSharedMemorySize, SM0);
    cudaFuncSetAttribute(gemm_k<D1, D2, true>,   cudaFuncAttributeMaxDynamicSharedMemorySize, SM1);
    cudaFuncSetAttribute(gemm_k<D2, CMB, false>, cudaFuncAttributeMaxDynamicSharedMemorySize, SM2);
    cudaFuncSetAttribute(gemm_k<D3, D4, false>,  cudaFuncAttributeMaxDynamicSharedMemorySize, SM3);

    const int GB = NNODES / 128;  // 1152 blocks per GEMM

    // L0: t0 = x@w0 + b0 (+stats)
    gemm_k<D0, D1, true><<<GB, 256, SM0>>>(x, w0, b0, t0, part);
    stage2_k<<<2 * D1, 256>>>(part, stats, GB, 2 * D1);
    fold0_k<<<1, 256>>>(stats, gamma0, beta0, w1, b1, w1f, bias1);

    // L1: t1 = BN(t0)@w1 + b1 (+stats)
    gemm_k<D1, D2, true><<<GB, 256, SM1>>>(t0, w1f, bias1, t1, part);
    stage2_k<<<2 * D2, 256>>>(part, stats, GB, 2 * D2);
    fold1_k<<<1, 256>>>(stats, gamma1, beta1, g2, w2, b2, mu2, sigma2, wcf, biasc, gw);

    // L2a: xr = BN(t1)@[g2|w2] + bias
    gemm_k<D2, CMB, false><<<GB, 256, SM2>>>(t1, wcf, biasc, xr, nullptr);
    // L2b: 9-point grid stencil + mean-aggregate + root (+stats)
    stencil_k<<<(NNODES * D3) / 256, 256>>>(xr, gw, h2, part);
    stage2_k<<<2 * D3, 256>>>(part, stats, (NNODES * D3) / 256, 2 * D3);
    fold2_k<<<1, 256>>>(stats, gamma2, beta2, w3, b3, w3f, bias3);

    // L3: out = BN(h2)@w3 + b3
    gemm_k<D3, D4, false><<<GB, 256, SM3>>>(h2, w3f, bias3, out, nullptr);
}

// round 3
// speedup vs baseline: 1.0334x; 1.0334x over previous
#include <cuda_runtime.h>
#include <math.h>

// ---------------- problem constants ----------------
#define NNODES 147456
#define GDIM   48
#define NPB    2304          // nodes per batch (48*48)
#define D0 128
#define D1 102
#define D2 73
#define D3 44
#define D4 16
#define KK 3
#define XG (KK*D3)           // 132
#define CMB (XG+D3)          // 176

// ---------------- scratch (device globals; allocation-free) ----------------
__device__ float g_t0[NNODES*D1];
__device__ float g_t1[NNODES*D2];
__device__ float g_xr[NNODES*CMB];
__device__ float g_h2[NNODES*D3];
__device__ float g_part[25344*88];
__device__ float g_stats[256];
__device__ float g_w1f[D1*D2];
__device__ float g_bias1[D2];
__device__ float g_wcf[D2*CMB];
__device__ float g_biasc[CMB];
__device__ float g_w3f[D3*D4];
__device__ float g_bias3[D4];
__device__ float g_gw[27];

// ---------------- helpers ----------------
__host__ __device__ constexpr int kpad16(int k) { return (k + 15) / 16 * 16; }
__host__ __device__ constexpr int gemm2_smem_bytes(int K, int NCB, bool S) {
    return (kpad16(K) * NCB + 2 * 16 * 132 + (S ? 2 * NCB : 0)) * 4;
}

__device__ __forceinline__ unsigned long long f32x2_dup(float w) {
    unsigned long long r;
    asm("mov.b64 %0, {%1, %1};" : "=l"(r) : "f"(w));
    return r;
}
__device__ __forceinline__ void ffma2(unsigned long long& d,
                                      unsigned long long a,
                                      unsigned long long b) {
    asm("fma.rn.f32x2 %0, %1, %2, %0;" : "+l"(d) : "l"(a), "l"(b));
}

// stage one 16-k tile of A, transposed to dst[kk*132 + r], via cp.async
template <int K>
__device__ __forceinline__ void stage_tile(const float* __restrict__ A, int row0,
                                           int t, float* dst, int tid) {
#pragma unroll
    for (int i = 0; i < 8; i++) {
        int e = tid + i * 256;
        int r = e >> 4, kk = e & 15;
        int k = t * 16 + kk;
        float* d = dst + kk * 132 + r;
        if (k < K) {
            unsigned sa = (unsigned)__cvta_generic_to_shared(d);
            asm volatile("cp.async.ca.shared.global [%0], [%1], 4;"
                         :: "r"(sa), "l"(A + (long)(row0 + r) * K + k));
        } else {
            *d = 0.f;
        }
    }
}

// ---------------- GEMM: C[N x NCT] = A[N x K] @ W[K x NCT] + bias ----------------
// 128 rows per block, 256 threads. Column slice of width NCB at c0 = by*NCB.
// Thread micro-tile = 8 rows (as 4 f32x2 pairs) x TN cols. FFMA2 inner loop,
// cp.async double-buffered A staging. Optional per-block BN (sum,sumsq) partials.
template <int K, int NCT, int NCB, bool STATS>
__global__ void __launch_bounds__(256)
gemm2_k(const float* __restrict__ A, const float* __restrict__ W,
        const float* __restrict__ bias, float* __restrict__ C,
        float* __restrict__ part) {
    constexpr int KP = kpad16(K);
    constexpr int NT = KP / 16;
    constexpr int TN = (NCB + 15) / 16;

    extern __shared__ float sm[];
    float* Ws   = sm;                      // KP * NCB
    float* As   = Ws + KP * NCB;           // 2 x [16][132]
    float* ssum = As + 2 * 16 * 132;       // NCB (STATS)
    float* ssq  = ssum + NCB;              // NCB (STATS)

    const int tid = threadIdx.x;
    const int tx  = tid & 15;
    const int ty  = tid >> 4;
    const int row0 = blockIdx.x * 128;
    const int c0   = blockIdx.y * NCB;

    // stage weight slice (zero-padded rows K..KP-1 and cols beyond NCT)
    for (int e = tid; e < KP * NCB; e += 256) {
        int k = e / NCB, c = e - k * NCB;
        Ws[e] = (k < K && c0 + c < NCT) ? W[(long)k * NCT + c0 + c] : 0.f;
    }
    if (STATS) for (int e = tid; e < 2 * NCB; e += 256) ssum[e] = 0.f;

    int cols[TN];
#pragma unroll
    for (int j = 0; j < TN; j++) {
        int c = tx + 16 * j;
        cols[j] = (c < NCB) ? c : 0;
    }

    unsigned long long acc[4][TN];
#pragma unroll
    for (int i = 0; i < 4; i++)
#pragma unroll
        for (int j = 0; j < TN; j++) acc[i][j] = 0ULL;

    // prologue: stage tile 0
    stage_tile<K>(A, row0, 0, As, tid);
    asm volatile("cp.async.commit_group;" ::: "memory");
    asm volatile("cp.async.wait_group 0;" ::: "memory");
    __syncthreads();

    for (int t = 0; t < NT; t++) {
        float* buf = As + (t & 1) * (16 * 132);
        if (t + 1 < NT)
            stage_tile<K>(A, row0, t + 1, As + ((t + 1) & 1) * (16 * 132), tid);
        asm volatile("cp.async.commit_group;" ::: "memory");

#pragma unroll
        for (int kk = 0; kk < 16; kk++) {
            const ulonglong2 u0 = *(const ulonglong2*)&buf[kk * 132 + ty * 8];
            const ulonglong2 u1 = *(const ulonglong2*)&buf[kk * 132 + ty * 8 + 4];
            const float* wr = &Ws[(t * 16 + kk) * NCB];
#pragma unroll
            for (int j = 0; j < TN; j++) {
                unsigned long long w2 = f32x2_dup(wr[cols[j]]);
                ffma2(acc[0][j], u0.x, w2);
                ffma2(acc[1][j], u0.y, w2);
                ffma2(acc[2][j], u1.x, w2);
                ffma2(acc[3][j], u1.y, w2);
            }
        }
        asm volatile("cp.async.wait_group 0;" ::: "memory");
        __syncthreads();
    }

    // epilogue: bias, store, local stats
#pragma unroll
    for (int j = 0; j < TN; j++) {
        int c = tx + 16 * j;
        if (c < NCB && c0 + c < NCT) {
            float bv = bias[c0 + c];
            float s = 0.f, q = 0.f;
#pragma unroll
            for (int i = 0; i < 4; i++) {
                float lo = __uint_as_float((unsigned)acc[i][j]);
                float hi = __uint_as_float((unsigned)(acc[i][j] >> 32));
                float v0 = lo + bv, v1 = hi + bv;
                C[(long)(row0 + ty * 8 + 2 * i)     * NCT + c0 + c] = v0;
                C[(long)(row0 + ty * 8 + 2 * i + 1) * NCT + c0 + c] = v1;
                s += v0 + v1; q += v0 * v0 + v1 * v1;
            }
            if (STATS) { atomicAdd(&ssum[c], s); atomicAdd(&ssq[c], q); }
        }
    }
    if (STATS) {
        __syncthreads();
        for (int c = tid; c < NCB; c += 256) {
            part[(size_t)blockIdx.x * (2 * NCB) + c]       = ssum[c];
            part[(size_t)blockIdx.x * (2 * NCB) + NCB + c] = ssq[c];
        }
    }
}

// ---------------- stage-2 reduction of per-block partials ----------------
__global__ void stage2_k(const float* __restrict__ part, float* __restrict__ stats,
                         int P, int C2) {
    int c = blockIdx.x;
    float s = 0.f;
    for (int p = threadIdx.x; p < P; p += 256) s += part[(size_t)p * C2 + c];
    __shared__ float sm[256];
    sm[threadIdx.x] = s; __syncthreads();
    for (int off = 128; off > 0; off >>= 1) {
        if (threadIdx.x < off) sm[threadIdx.x] += sm[threadIdx.x + off];
        __syncthreads();
    }
    if (threadIdx.x == 0) stats[c] = sm[0];
}

// ---------------- BN fold kernels ----------------
__global__ void fold0_k(const float* __restrict__ stats,
                        const float* __restrict__ gamma, const float* __restrict__ beta,
                        const float* __restrict__ w1, const float* __restrict__ b1,
                        float* __restrict__ w1f, float* __restrict__ bias1) {
    __shared__ float s0[D1], c0[D1];
    int tid = threadIdx.x;
    for (int c = tid; c < D1; c += 256) {
        float m = stats[c] * (1.f / NNODES);
        float v = stats[D1 + c] * (1.f / NNODES) - m * m;
        float s = gamma[c] * rsqrtf(v + 1e-5f);
        s0[c] = s; c0[c] = beta[c] - m * s;
    }
    __syncthreads();
    for (int e = tid; e < D1 * D2; e += 256) {
        int k = e / D2;
        w1f[e] = s0[k] * w1[e];
    }
    for (int j = tid; j < D2; j += 256) {
        float b = b1[j];
        for (int k = 0; k < D1; k++) b += c0[k] * w1[k * D2 + j];
        bias1[j] = b;
    }
}

__global__ void fold1_k(const float* __restrict__ stats,
                        const float* __restrict__ gamma, const float* __restrict__ beta,
                        const float* __restrict__ g2, const float* __restrict__ w2,
                        const float* __restrict__ b2,
                        const float* __restrict__ mu, const float* __restrict__ sigma,
                        float* __restrict__ wcf, float* __restrict__ biasc,
                        float* __restrict__ gw) {
    __shared__ float s1[D2], c1[D2];
    int tid = threadIdx.x;
    for (int c = tid; c < D2; c += 256) {
        float m = stats[c] * (1.f / NNODES);
        float v = stats[D2 + c] * (1.f / NNODES) - m * m;
        float s = gamma[c] * rsqrtf(v + 1e-5f);
        s1[c] = s; c1[c] = beta[c] - m * s;
    }
    __syncthreads();
    for (int e = tid; e < D2 * CMB; e += 256) {
        int k = e / CMB, j = e - k * CMB;
        float w = (j < XG) ? g2[k * XG + j] : w2[k * D3 + (j - XG)];
        wcf[e] = s1[k] * w;
    }
    for (int j = tid; j < CMB; j += 256) {
        float b = (j < XG) ? 0.f : b2[j - XG];
        for (int k = 0; k < D2; k++)
            b += c1[k] * ((j < XG) ? g2[k * XG + j] : w2[k * D3 + (j - XG)]);
        biasc[j] = b;
    }
    if (tid < 27) {
        int ci = tid / 3, k = tid % 3;
        int dx = ci / 3 - 1, dy = ci % 3 - 1;
        float ex = dx * 0.5f + 0.5f - mu[k * 2 + 0];
        float ey = dy * 0.5f + 0.5f - mu[k * 2 + 1];
        float sx = sigma[k * 2 + 0], sy = sigma[k * 2 + 1];
        gw[tid] = expf(-0.5f * (ex * ex / (1e-15f + sx * sx) +
                                ey * ey / (1e-15f + sy * sy)));
    }
}

__global__ void fold2_k(const float* __restrict__ stats,
                        const float* __restrict__ gamma, const float* __restrict__ beta,
                        const float* __restrict__ w3, const float* __restrict__ b3,
                        float* __restrict__ w3f, float* __restrict__ bias3) {
    __shared__ float s2[D3], c2[D3];
    int tid = threadIdx.x;
    for (int c = tid; c < D3; c += 256) {
        float m = stats[c] * (1.f / NNODES);
        float v = stats[D3 + c] * (1.f / NNODES) - m * m;
        float s = gamma[c] * rsqrtf(v + 1e-5f);
        s2[c] = s; c2[c] = beta[c] - m * s;
    }
    __syncthreads();
    for (int e = tid; e < D3 * D4; e += 256) {
        int k = e / D4;
        w3f[e] = s2[k] * w3[e];
    }
    for (int j = tid; j < D4; j += 256) {
        float b = b3[j];
        for (int k = 0; k < D3; k++) b += c2[k] * w3[k * D4 + j];
        bias3[j] = b;
    }
}

// ---------------- 9-point stencil (the GMM conv aggregation) ----------------
__global__ void __launch_bounds__(256)
stencil_k(const float* __restrict__ xr, const float* __restrict__ gw9,
          float* __restrict__ h2, float* __restrict__ part) {
    __shared__ float gws[27];
    __shared__ float ssum[D3], ssq[D3];
    int tid = threadIdx.x;
    if (tid < 27) gws[tid] = gw9[tid];
    if (tid < D3) { ssum[tid] = 0.f; ssq[tid] = 0.f; }
    __syncthreads();

    long idx = (long)blockIdx.x * 256 + tid;   // < N*44 exactly
    int node = (int)(idx / D3);
    int o    = (int)(idx - (long)node * D3);
    int r  = node % NPB;
    int ix = r / GDIM, iy = r % GDIM;

    int nvx = 3 - (ix == 0) - (ix == GDIM - 1);
    int nvy = 3 - (iy == 0) - (iy == GDIM - 1);
    float inv_cnt = 1.f / (float)(nvx * nvy);

    float acc = 0.f;
#pragma unroll
    for (int dx = -1; dx <= 1; dx++) {
        int jx = ix + dx;
        if (jx < 0 || jx >= GDIM) continue;
#pragma unroll
        for (int dy = -1; dy <= 1; dy++) {
            int jy = iy + dy;
            if (jy < 0 || jy >= GDIM) continue;
            const float* row = xr + (long)(node + dx * GDIM + dy) * CMB;
            const float* g   = gws + ((dx + 1) * 3 + (dy + 1)) * 3;
            acc += row[o] * g[0] + row[D3 + o] * g[1] + row[2 * D3 + o] * g[2];
        }
    }
    float v = acc * inv_cnt + xr[(long)node * CMB + XG + o];
    h2[idx] = v;
    atomicAdd(&ssum[o], v);
    atomicAdd(&ssq[o], v * v);
    __syncthreads();
    if (tid < D3) {
        part[(size_t)blockIdx.x * (2 * D3) + tid]      = ssum[tid];
        part[(size_t)blockIdx.x * (2 * D3) + D3 + tid] = ssq[tid];
    }
}

// ---------------- host launcher ----------------
extern "C" void kernel_launch(void* const* d_in, const int* in_sizes, int n_in,
                              void* d_out, int out_size) {
    const float* x      = (const float*)d_in[0];
    const float* w0     = (const float*)d_in[3];
    const float* b0     = (const float*)d_in[4];
    const float* gamma0 = (const float*)d_in[5];
    const float* beta0  = (const float*)d_in[6];
    const float* w1     = (const float*)d_in[7];
    const float* b1     = (const float*)d_in[8];
    const float* gamma1 = (const float*)d_in[9];
    const float* beta1  = (const float*)d_in[10];
    const float* w2     = (const float*)d_in[11];
    const float* g2     = (const float*)d_in[12];
    const float* mu2    = (const float*)d_in[13];
    const float* sigma2 = (const float*)d_in[14];
    const float* b2     = (const float*)d_in[15];
    const float* gamma2 = (const float*)d_in[16];
    const float* beta2  = (const float*)d_in[17];
    const float* w3     = (const float*)d_in[18];
    const float* b3     = (const float*)d_in[19];
    float* out = (float*)d_out;

    float *t0, *t1, *xr, *h2, *part, *stats, *w1f, *bias1, *wcf, *biasc, *w3f, *bias3, *gw;
    cudaGetSymbolAddress((void**)&t0,    g_t0);
    cudaGetSymbolAddress((void**)&t1,    g_t1);
    cudaGetSymbolAddress((void**)&xr,    g_xr);
    cudaGetSymbolAddress((void**)&h2,    g_h2);
    cudaGetSymbolAddress((void**)&part,  g_part);
    cudaGetSymbolAddress((void**)&stats, g_stats);
    cudaGetSymbolAddress((void**)&w1f,   g_w1f);
    cudaGetSymbolAddress((void**)&bias1, g_bias1);
    cudaGetSymbolAddress((void**)&wcf,   g_wcf);
    cudaGetSymbolAddress((void**)&biasc, g_biasc);
    cudaGetSymbolAddress((void**)&w3f,   g_w3f);
    cudaGetSymbolAddress((void**)&bias3, g_bias3);
    cudaGetSymbolAddress((void**)&gw,    g_gw);

    constexpr int SM0 = gemm2_smem_bytes(D0, D1, true);
    constexpr int SM1 = gemm2_smem_bytes(D1, D2, true);
    constexpr int SM2 = gemm2_smem_bytes(D2, 88, false);
    constexpr int SM3 = gemm2_smem_bytes(D3, D4, false);
    cudaFuncSetAttribute(gemm2_k<D0, D1, D1, true>,    cudaFuncAttributeMaxDynamicSharedMemorySize, SM0);
    cudaFuncSetAttribute(gemm2_k<D1, D2, D2, true>,    cudaFuncAttributeMaxDynamicSharedMemorySize, SM1);
    cudaFuncSetAttribute(gemm2_k<D2, CMB, 88, false>,  cudaFuncAttributeMaxDynamicSharedMemorySize, SM2);
    cudaFuncSetAttribute(gemm2_k<D3, D4, D4, false>,   cudaFuncAttributeMaxDynamicSharedMemorySize, SM3);

    const int GB = NNODES / 128;  // 1152 row-blocks per GEMM

    // L0: t0 = x@w0 + b0 (+stats)
    gemm2_k<D0, D1, D1, true><<<GB, 256, SM0>>>(x, w0, b0, t0, part);
    stage2_k<<<2 * D1, 256>>>(part, stats, GB, 2 * D1);
    fold0_k<<<1, 256>>>(stats, gamma0, beta0, w1, b1, w1f, bias1);

    // L1: t1 = BN(t0)@w1 + b1 (+stats)
    gemm2_k<D1, D2, D2, true><<<GB, 256, SM1>>>(t0, w1f, bias1, t1, part);
    stage2_k<<<2 * D2, 256>>>(part, stats, GB, 2 * D2);
    fold1_k<<<1, 256>>>(stats, gamma1, beta1, g2, w2, b2, mu2, sigma2, wcf, biasc, gw);

    // L2a: xr = BN(t1)@[g2|w2] + bias  (two 88-column slices)
    gemm2_k<D2, CMB, 88, false><<<dim3(GB, 2), 256, SM2>>>(t1, wcf, biasc, xr, nullptr);
    // L2b: 9-point grid stencil + mean-aggregate + root (+stats)
    stencil_k<<<(NNODES * D3) / 256, 256>>>(xr, gw, h2, part);
    stage2_k<<<2 * D3, 256>>>(part, stats, (NNODES * D3) / 256, 2 * D3);
    fold2_k<<<1, 256>>>(stats, gamma2, beta2, w3, b3, w3f, bias3);

    // L3: out = BN(h2)@w3 + b3
    gemm2_k<D3, D4, D4, false><<<GB, 256, SM3>>>(h2, w3f, bias3, out, nullptr);
}

// round 15
// speedup vs baseline: 1.2601x; 1.2194x over previous
#include <cuda_runtime.h>
#include <cuda_bf16.h>
#include <stdint.h>
#include <math.h>

// ---------------- problem constants ----------------
#define NNODES 147456
#define GDIM   48
#define NPB    2304
#define D0 128
#define D1 102
#define D2 73
#define D3 44
#define D4 16
#define KK 3
#define XG (KK*D3)           // 132
#define CMB (XG+D3)          // 176

// ---------------- scratch (device globals; allocation-free) ----------------
__device__ float g_t0[NNODES*D1];
__device__ float g_t1[NNODES*D2];
__device__ float g_xr[NNODES*CMB];
__device__ float g_h2[NNODES*D3];
__device__ float g_part[25344*88];
__device__ float g_stats[256];
__device__ float g_bias1[D2];
__device__ float g_biasc[CMB];
__device__ float g_w3f[D3*D4];
__device__ float g_bias3[D4];
__device__ float g_gw[27];
// split bf16 weights, [NCP rows (n)][128 cols (k)], zero-padded
__device__ __nv_bfloat16 g_w0h[104*128], g_w0l[104*128];
__device__ __nv_bfloat16 g_w1h[80*128],  g_w1l[80*128];
__device__ __nv_bfloat16 g_wch[176*128], g_wcl[176*128];

// ---------------- warp-MMA helpers (baseline PTX, no 'a' features) ----------
__device__ __forceinline__ uint32_t smem_u32(const void* p) {
    uint32_t a;
    asm("{ .reg .u64 t; cvta.to.shared.u64 t, %1; cvt.u32.u64 %0, t; }" : "=r"(a) : "l"(p));
    return a;
}
#define LDSM4(r, a) \
    asm volatile("ldmatrix.sync.aligned.m8n8.x4.shared.b16 {%0,%1,%2,%3}, [%4];" \
        : "=r"((r)[0]),"=r"((r)[1]),"=r"((r)[2]),"=r"((r)[3]) : "r"(a))
#define LDSM2(r, a) \
    asm volatile("ldmatrix.sync.aligned.m8n8.x2.shared.b16 {%0,%1}, [%2];" \
        : "=r"((r)[0]),"=r"((r)[1]) : "r"(a))
__device__ __forceinline__ void mma16816(float* d, const uint32_t* a, const uint32_t* b) {
    asm volatile(
        "mma.sync.aligned.m16n8k16.row.col.f32.bf16.bf16.f32 "
        "{%0,%1,%2,%3}, {%4,%5,%6,%7}, {%8,%9}, {%0,%1,%2,%3};"
        : "+f"(d[0]), "+f"(d[1]), "+f"(d[2]), "+f"(d[3])
        : "r"(a[0]), "r"(a[1]), "r"(a[2]), "r"(a[3]), "r"(b[0]), "r"(b[1]));
}

// ================= warp-MMA split-bf16 GEMM =================
// C[N x NCT] = A[N x K] @ W[K x NCT] + bias. fp32 in/out.
// A split to (hi,lo) bf16 on the fly into smem; W pre-split [NCP][128].
// D = Ahi*Whi + Ahi*Wlo + Alo*Whi (fp32 accum). 128 rows/CTA, 8 warps x 16 rows.
template <int K, int NCT, int NCP, bool STATS>
__global__ void __launch_bounds__(256)
mmagemm_k(const float* __restrict__ A, const __nv_bfloat16* __restrict__ Bh,
          const __nv_bfloat16* __restrict__ Bl, const float* __restrict__ bias,
          float* __restrict__ C, float* __restrict__ part) {
    constexpr int KP   = (K + 15) / 16 * 16;   // padded K
    constexpr int NKS  = KP / 16;              // k-steps
    constexpr int NK8  = KP / 8;               // 8-elem chunks per row
    constexpr int NT   = NCP / 8;              // n-tiles of 8
    constexpr int STR  = KP + 8;               // smem row stride (bf16 elems)
    constexpr int NCS  = NCT | 1;              // epi row stride (floats)
    // smem byte offsets
    constexpr int A_HI = 0;
    constexpr int A_SZ = 128 * STR * 2;
    constexpr int A_LO = A_HI + A_SZ;
    constexpr int B_HI = A_LO + A_SZ;
    constexpr int B_SZ = NCP * STR * 2;
    constexpr int B_LO = B_HI + B_SZ;

    extern __shared__ char smem[];
    const uint32_t sb = smem_u32(smem);
    const int tid  = threadIdx.x;
    const int w    = tid >> 5;
    const int lane = tid & 31;
    const int row0 = blockIdx.x * 128;

    // ---- stage weights: [n][k] row-major, 16B chunks, padded stride ----
    const uint4* bh4 = (const uint4*)Bh;
    const uint4* bl4 = (const uint4*)Bl;
    for (int ch = tid; ch < NCP * NK8; ch += 256) {
        int n = ch / NK8, k8 = ch - n * NK8;
        int dst = (n * STR + k8 * 8) * 2;
        *(uint4*)(smem + B_HI + dst) = bh4[n * 16 + k8];  // global row stride = 128 bf16
        *(uint4*)(smem + B_LO + dst) = bl4[n * 16 + k8];
    }

    // ---- stage A with on-the-fly bf16 hi/lo split ----
    for (int ch = tid; ch < 128 * NK8; ch += 256) {
        int r = ch / NK8, k8 = ch - r * NK8;
        int k0 = k8 * 8;
        const float* arow = A + (long)(row0 + r) * K;
        uint4 uh, ul;
        __nv_bfloat16* hh = (__nv_bfloat16*)&uh;
        __nv_bfloat16* ll = (__nv_bfloat16*)&ul;
#pragma unroll
        for (int j = 0; j < 8; j++) {
            int k = k0 + j;
            float v = (k < K) ? arow[k] : 0.f;
            __nv_bfloat16 h = __float2bfloat16(v);
            hh[j] = h;
            ll[j] = __float2bfloat16(v - __bfloat162float(h));
        }
        int dst = (r * STR + k0) * 2;
        *(uint4*)(smem + A_HI + dst) = uh;
        *(uint4*)(smem + A_LO + dst) = ul;
    }
    __syncthreads();

    // ---- warp MMA mainloop ----
    float acc[NT][4];
#pragma unroll
    for (int nt = 0; nt < NT; nt++)
#pragma unroll
        for (int i = 0; i < 4; i++) acc[nt][i] = 0.f;

    // ldmatrix addresses
    const uint32_t a_off = ((w * 16 + (lane & 15)) * STR + (lane >> 4) * 8) * 2;
    const uint32_t b_off = (((lane & 7)) * STR + ((lane >> 3) & 1) * 8) * 2;

    for (int ks = 0; ks < NKS; ks++) {
        uint32_t ah[4], al[4];
        LDSM4(ah, sb + A_HI + a_off + ks * 32);
        LDSM4(al, sb + A_LO + a_off + ks * 32);
#pragma unroll
        for (int nt = 0; nt < NT; nt++) {
            uint32_t bh[2], bl[2];
            const uint32_t bo = b_off + nt * (8 * STR * 2) + ks * 32;
            LDSM2(bh, sb + B_HI + bo);
            LDSM2(bl, sb + B_LO + bo);
            mma16816(acc[nt], ah, bh);
            mma16816(acc[nt], ah, bl);
            mma16816(acc[nt], al, bh);
        }
    }
    __syncthreads();   // done reading tiles; smem is reused below

    // ---- epilogue: fragments -> smem (+bias) ----
    float* epi = (float*)smem;   // 128 x NCS floats (fits in tile region)
    const int er0 = w * 16 + (lane >> 2);
    const int ec0 = (lane & 3) * 2;
#pragma unroll
    for (int nt = 0; nt < NT; nt++) {
        int c = nt * 8 + ec0;
        if (c < NCT) {
            float b0 = bias[c];
            float b1 = (c + 1 < NCT) ? bias[c + 1] : 0.f;
            epi[er0 * NCS + c]           = acc[nt][0] + b0;
            if (c + 1 < NCT) epi[er0 * NCS + c + 1] = acc[nt][1] + b1;
            epi[(er0 + 8) * NCS + c]     = acc[nt][2] + b0;
            if (c + 1 < NCT) epi[(er0 + 8) * NCS + c + 1] = acc[nt][3] + b1;
        }
    }
    __syncthreads();

    // ---- coalesced store + per-column BN stats ----
    const long base = (long)row0 * NCT;
    for (int i2 = tid; i2 < 64 * NCT; i2 += 256) {
        int g = i2 * 2;
        int r = g / NCT, c = g - r * NCT;
        float v0 = epi[r * NCS + c];
        int c1 = c + 1, r1 = r;
        if (c1 == NCT) { c1 = 0; r1 = r + 1; }
        float v1 = epi[r1 * NCS + c1];
        *(float2*)(C + base + g) = make_float2(v0, v1);
    }
    if (STATS) {
        for (int c = tid; c < NCT; c += 256) {
            float s = 0.f, q = 0.f;
#pragma unroll 4
            for (int r = 0; r < 128; r++) {
                float v = epi[r * NCS + c];
                s += v; q += v * v;
            }
            part[(size_t)blockIdx.x * (2 * NCT) + c]       = s;
            part[(size_t)blockIdx.x * (2 * NCT) + NCT + c] = q;
        }
    }
}

// ---------------- weight split helper ----------------
__device__ __forceinline__ void split_bf16(float w, __nv_bfloat16* ph, __nv_bfloat16* pl) {
    __nv_bfloat16 h = __float2bfloat16(w);
    *ph = h;
    *pl = __float2bfloat16(w - __bfloat162float(h));
}

// prep: split w0 [128,102] -> [104 rows(n)][128 cols(k)] bf16 hi/lo
__global__ void prep0_k(const float* __restrict__ w0,
                        __nv_bfloat16* __restrict__ wh, __nv_bfloat16* __restrict__ wl) {
    for (int e = threadIdx.x + blockIdx.x * 256; e < 104 * 128; e += gridDim.x * 256) {
        int n = e >> 7, k = e & 127;
        float w = (n < D1) ? w0[k * D1 + n] : 0.f;
        split_bf16(w, &wh[e], &wl[e]);
    }
}

// ---------------- stage-2 reduction of per-block partials ----------------
__global__ void stage2_k(const float* __restrict__ part, float* __restrict__ stats,
                         int P, int C2) {
    int c = blockIdx.x;
    float s = 0.f;
    for (int p = threadIdx.x; p < P; p += 256) s += part[(size_t)p * C2 + c];
    __shared__ float sm[256];
    sm[threadIdx.x] = s; __syncthreads();
    for (int off = 128; off > 0; off >>= 1) {
        if (threadIdx.x < off) sm[threadIdx.x] += sm[threadIdx.x + off];
        __syncthreads();
    }
    if (threadIdx.x == 0) stats[c] = sm[0];
}

// ---------------- BN fold kernels (emit split bf16 [n][k] weights) ----------
__global__ void fold0_k(const float* __restrict__ stats,
                        const float* __restrict__ gamma, const float* __restrict__ beta,
                        const float* __restrict__ w1, const float* __restrict__ b1,
                        __nv_bfloat16* __restrict__ wh, __nv_bfloat16* __restrict__ wl,
                        float* __restrict__ bias1) {
    __shared__ float s0[D1], c0[D1];
    int tid = threadIdx.x;
    for (int c = tid; c < D1; c += 256) {
        float m = stats[c] * (1.f / NNODES);
        float v = stats[D1 + c] * (1.f / NNODES) - m * m;
        float s = gamma[c] * rsqrtf(v + 1e-5f);
        s0[c] = s; c0[c] = beta[c] - m * s;
    }
    __syncthreads();
    for (int e = tid; e < 80 * 128; e += 256) {
        int n = e >> 7, k = e & 127;
        float w = (n < D2 && k < D1) ? s0[k] * w1[k * D2 + n] : 0.f;
        split_bf16(w, &wh[e], &wl[e]);
    }
    for (int j = tid; j < D2; j += 256) {
        float b = b1[j];
        for (int k = 0; k < D1; k++) b += c0[k] * w1[k * D2 + j];
        bias1[j] = b;
    }
}

__global__ void fold1_k(const float* __restrict__ stats,
                        const float* __restrict__ gamma, const float* __restrict__ beta,
                        const float* __restrict__ g2, const float* __restrict__ w2,
                        const float* __restrict__ b2,
                        const float* __restrict__ mu, const float* __restrict__ sigma,
                        __nv_bfloat16* __restrict__ wh, __nv_bfloat16* __restrict__ wl,
                        float* __restrict__ biasc, float* __restrict__ gw) {
    __shared__ float s1[D2], c1[D2];
    int tid = threadIdx.x;
    for (int c = tid; c < D2; c += 256) {
        float m = stats[c] * (1.f / NNODES);
        float v = stats[D2 + c] * (1.f / NNODES) - m * m;
        float s = gamma[c] * rsqrtf(v + 1e-5f);
        s1[c] = s; c1[c] = beta[c] - m * s;
    }
    __syncthreads();
    for (int e = tid; e < 176 * 128; e += 256) {
        int n = e >> 7, k = e & 127;
        float w = 0.f;
        if (k < D2) w = s1[k] * ((n < XG) ? g2[k * XG + n] : w2[k * D3 + (n - XG)]);
        split_bf16(w, &wh[e], &wl[e]);
    }
    for (int j = tid; j < CMB; j += 256) {
        float b = (j < XG) ? 0.f : b2[j - XG];
        for (int k = 0; k < D2; k++)
            b += c1[k] * ((j < XG) ? g2[k * XG + j] : w2[k * D3 + (j - XG)]);
        biasc[j] = b;
    }
    if (tid < 27) {
        int ci = tid / 3, k = tid % 3;
        int dx = ci / 3 - 1, dy = ci % 3 - 1;
        float ex = dx * 0.5f + 0.5f - mu[k * 2 + 0];
        float ey = dy * 0.5f + 0.5f - mu[k * 2 + 1];
        float sx = sigma[k * 2 + 0], sy = sigma[k * 2 + 1];
        gw[tid] = expf(-0.5f * (ex * ex / (1e-15f + sx * sx) +
                                ey * ey / (1e-15f + sy * sy)));
    }
}

__global__ void fold2_k(const float* __restrict__ stats,
                        const float* __restrict__ gamma, const float* __restrict__ beta,
                        const float* __restrict__ w3, const float* __restrict__ b3,
                        float* __restrict__ w3f, float* __restrict__ bias3) {
    __shared__ float s2[D3], c2[D3];
    int tid = threadIdx.x;
    for (int c = tid; c < D3; c += 256) {
        float m = stats[c] * (1.f / NNODES);
        float v = stats[D3 + c] * (1.f / NNODES) - m * m;
        float s = gamma[c] * rsqrtf(v + 1e-5f);
        s2[c] = s; c2[c] = beta[c] - m * s;
    }
    __syncthreads();
    for (int e = tid; e < D3 * D4; e += 256) {
        int k = e / D4;
        w3f[e] = s2[k] * w3[e];
    }
    for (int j = tid; j < D4; j += 256) {
        float b = b3[j];
        for (int k = 0; k < D3; k++) b += c2[k] * w3[k * D4 + j];
        bias3[j] = b;
    }
}

// ---------------- 9-point stencil (GMM conv aggregation) ----------------
__global__ void __launch_bounds__(256)
stencil_k(const float* __restrict__ xr, const float* __restrict__ gw9,
          float* __restrict__ h2, float* __restrict__ part) {
    __shared__ float gws[27];
    __shared__ float ssum[D3], ssq[D3];
    int tid = threadIdx.x;
    if (tid < 27) gws[tid] = gw9[tid];
    if (tid < D3) { ssum[tid] = 0.f; ssq[tid] = 0.f; }
    __syncthreads();

    long idx = (long)blockIdx.x * 256 + tid;   // < N*44 exactly
    int node = (int)(idx / D3);
    int o    = (int)(idx - (long)node * D3);
    int r  = node % NPB;
    int ix = r / GDIM, iy = r % GDIM;

    int nvx = 3 - (ix == 0) - (ix == GDIM - 1);
    int nvy = 3 - (iy == 0) - (iy == GDIM - 1);
    float inv_cnt = 1.f / (float)(nvx * nvy);

    float acc = 0.f;
#pragma unroll
    for (int dx = -1; dx <= 1; dx++) {
        int jx = ix + dx;
        if (jx < 0 || jx >= GDIM) continue;
#pragma unroll
        for (int dy = -1; dy <= 1; dy++) {
            int jy = iy + dy;
            if (jy < 0 || jy >= GDIM) continue;
            const float* rowp = xr + (long)(node + dx * GDIM + dy) * CMB;
            const float* g    = gws + ((dx + 1) * 3 + (dy + 1)) * 3;
            acc += rowp[o] * g[0] + rowp[D3 + o] * g[1] + rowp[2 * D3 + o] * g[2];
        }
    }
    float v = acc * inv_cnt + xr[(long)node * CMB + XG + o];
    h2[idx] = v;
    atomicAdd(&ssum[o], v);
    atomicAdd(&ssq[o], v * v);
    __syncthreads();
    if (tid < D3) {
        part[(size_t)blockIdx.x * (2 * D3) + tid]      = ssum[tid];
        part[(size_t)blockIdx.x * (2 * D3) + D3 + tid] = ssq[tid];
    }
}

// ---------------- small SIMT GEMM for L3 (44 -> 16) ----------------
__host__ __device__ constexpr int kpad16(int k) { return (k + 15) / 16 * 16; }
template <int K, int NC>
__global__ void __launch_bounds__(256)
gemm_small_k(const float* __restrict__ A, const float* __restrict__ W,
             const float* __restrict__ bias, float* __restrict__ C) {
    constexpr int KP = kpad16(K);
    __shared__ float Ws[KP * NC];
    __shared__ float As[16][132];
    const int tid = threadIdx.x;
    const int tx = tid & 15, ty = tid >> 4;
    const int row0 = blockIdx.x * 128;

    for (int e = tid; e < KP * NC; e += 256)
        Ws[e] = (e < K * NC) ? W[e] : 0.f;

    float acc[8];
#pragma unroll
    for (int i = 0; i < 8; i++) acc[i] = 0.f;

    for (int k0 = 0; k0 < KP; k0 += 16) {
        __syncthreads();
#pragma unroll
        for (int i = 0; i < 8; i++) {
            int e = tid + i * 256;
            int r = e >> 4, kk = e & 15;
            int k = k0 + kk;
            As[kk][r] = (k < K) ? A[(long)(row0 + r) * K + k] : 0.f;
        }
        __syncthreads();
#pragma unroll
        for (int kk = 0; kk < 16; kk++) {
            float w = Ws[(k0 + kk) * NC + tx];
            const float4 a0 = *(const float4*)&As[kk][ty * 8];
            const float4 a1 = *(const float4*)&As[kk][ty * 8 + 4];
            acc[0] += a0.x * w; acc[1] += a0.y * w; acc[2] += a0.z * w; acc[3] += a0.w * w;
            acc[4] += a1.x * w; acc[5] += a1.y * w; acc[6] += a1.z * w; acc[7] += a1.w * w;
        }
    }
    float bv = bias[tx];
#pragma unroll
    for (int i = 0; i < 8; i++)
        C[(long)(row0 + ty * 8 + i) * NC + tx] = acc[i] + bv;
}

// ---------------- host launcher ----------------
extern "C" void kernel_launch(void* const* d_in, const int* in_sizes, int n_in,
                              void* d_out, int out_size) {
    const float* x      = (const float*)d_in[0];
    const float* w0     = (const float*)d_in[3];
    const float* b0     = (const float*)d_in[4];
    const float* gamma0 = (const float*)d_in[5];
    const float* beta0  = (const float*)d_in[6];
    const float* w1     = (const float*)d_in[7];
    const float* b1     = (const float*)d_in[8];
    const float* gamma1 = (const float*)d_in[9];
    const float* beta1  = (const float*)d_in[10];
    const float* w2     = (const float*)d_in[11];
    const float* g2     = (const float*)d_in[12];
    const float* mu2    = (const float*)d_in[13];
    const float* sigma2 = (const float*)d_in[14];
    const float* b2     = (const float*)d_in[15];
    const float* gamma2 = (const float*)d_in[16];
    const float* beta2  = (const float*)d_in[17];
    const float* w3     = (const float*)d_in[18];
    const float* b3     = (const float*)d_in[19];
    float* out = (float*)d_out;

    float *t0, *t1, *xr, *h2, *part, *stats, *bias1, *biasc, *w3f, *bias3, *gw;
    __nv_bfloat16 *w0h, *w0l, *w1h, *w1l, *wch, *wcl;
    cudaGetSymbolAddress((void**)&t0,    g_t0);
    cudaGetSymbolAddress((void**)&t1,    g_t1);
    cudaGetSymbolAddress((void**)&xr,    g_xr);
    cudaGetSymbolAddress((void**)&h2,    g_h2);
    cudaGetSymbolAddress((void**)&part,  g_part);
    cudaGetSymbolAddress((void**)&stats, g_stats);
    cudaGetSymbolAddress((void**)&bias1, g_bias1);
    cudaGetSymbolAddress((void**)&biasc, g_biasc);
    cudaGetSymbolAddress((void**)&w3f,   g_w3f);
    cudaGetSymbolAddress((void**)&bias3, g_bias3);
    cudaGetSymbolAddress((void**)&gw,    g_gw);
    cudaGetSymbolAddress((void**)&w0h,   g_w0h);
    cudaGetSymbolAddress((void**)&w0l,   g_w0l);
    cudaGetSymbolAddress((void**)&w1h,   g_w1h);
    cudaGetSymbolAddress((void**)&w1l,   g_w1l);
    cudaGetSymbolAddress((void**)&wch,   g_wch);
    cudaGetSymbolAddress((void**)&wcl,   g_wcl);

    // smem = (128 + NCP) * (KP + 8) * 2 bytes * 2 (hi+lo)
    constexpr int SMB0 = (128 + 104) * (128 + 8) * 4;   // 126,208
    constexpr int SMB1 = (128 +  80) * (112 + 8) * 4;   //  99,840
    constexpr int SMB2 = (128 + 176) * ( 80 + 8) * 4;   // 107,008
    cudaFuncSetAttribute(mmagemm_k<D0, D1, 104, true>,
                         cudaFuncAttributeMaxDynamicSharedMemorySize, SMB0);
    cudaFuncSetAttribute(mmagemm_k<D1, D2, 80, true>,
                         cudaFuncAttributeMaxDynamicSharedMemorySize, SMB1);
    cudaFuncSetAttribute(mmagemm_k<D2, CMB, 176, false>,
                         cudaFuncAttributeMaxDynamicSharedMemorySize, SMB2);

    const int GB = NNODES / 128;  // 1152

    // prep: split w0
    prep0_k<<<16, 256>>>(w0, w0h, w0l);

    // L0: t0 = x@w0 + b0 (+stats)
    mmagemm_k<D0, D1, 104, true><<<GB, 256, SMB0>>>(x, w0h, w0l, b0, t0, part);
    stage2_k<<<2 * D1, 256>>>(part, stats, GB, 2 * D1);
    fold0_k<<<1, 256>>>(stats, gamma0, beta0, w1, b1, w1h, w1l, bias1);

    // L1: t1 = BN(t0)@w1 + b1 (+stats)
    mmagemm_k<D1, D2, 80, true><<<GB, 256, SMB1>>>(t0, w1h, w1l, bias1, t1, part);
    stage2_k<<<2 * D2, 256>>>(part, stats, GB, 2 * D2);
    fold1_k<<<1, 256>>>(stats, gamma1, beta1, g2, w2, b2, mu2, sigma2, wch, wcl, biasc, gw);

    // L2a: xr = BN(t1)@[g2|w2] + bias
    mmagemm_k<D2, CMB, 176, false><<<GB, 256, SMB2>>>(t1, wch, wcl, biasc, xr, nullptr);
    // L2b: 9-point grid stencil + mean-aggregate + root (+stats)
    stencil_k<<<(NNODES * D3) / 256, 256>>>(xr, gw, h2, part);
    stage2_k<<<2 * D3, 256>>>(part, stats, (NNODES * D3) / 256, 2 * D3);
    fold2_k<<<1, 256>>>(stats, gamma2, beta2, w3, b3, w3f, bias3);

    // L3: out = BN(h2)@w3 + b3
    gemm_small_k<D3, D4><<<GB, 256>>>(h2, w3f, bias3, out);
}